// round 13
// baseline (speedup 1.0000x reference)
#include <cuda_runtime.h>
#include <cuda_fp16.h>
#include <cstdint>
#include <cmath>

#define H_DIM 1024
#define I_DIM 2816
#define E_NUM 8
#define T_NUM 2048
#define SLOTS (T_NUM * 2)   // 4096 (every token has exactly 2 expert assignments)

// SMEM (half): 3-stage ring x (A 128x40 + B 128x40) halfs.
// PH=40 halfs = 80 B = 5x16B -> cp.async 16B dst stays aligned; fragment LDS
// banks (20g+tig) mod 32 are all distinct (conflict-free).
static constexpr int PH        = 40;
static constexpr int AS_H      = 128 * PH;            // 5120 halfs per operand
static constexpr int STAGE_H   = 2 * AS_H;            // 10240 halfs per stage
static constexpr int N_STAGE   = 3;
static constexpr int SMEM_BYTES = N_STAGE * STAGE_H * 2;  // 61440 B (x2 CTAs = 120KB/SM)

// ---------------- scratch (static __device__, allocation-free) ----------------
__device__ __half g_xh[T_NUM * H_DIM];          // x in fp16
__device__ __half g_gwh[E_NUM * I_DIM * H_DIM]; // gate_w fp16
__device__ __half g_uwh[E_NUM * I_DIM * H_DIM]; // up_w fp16
__device__ __half g_dwh[E_NUM * H_DIM * I_DIM]; // down_w fp16
__device__ float  g_gbuf[SLOTS * I_DIM];        // gate GEMM out (fp32, silu input)
__device__ __half g_hbuf[SLOTS * I_DIM];        // h = silu(gate)*up, fp16
__device__ int    g_counts[E_NUM];
__device__ int    g_offsets[E_NUM];
__device__ int    g_slot_token[SLOTS];
__device__ float  g_slot_wt[SLOTS];
__device__ int    g_assign_eid[SLOTS];
__device__ float  g_assign_wt[SLOTS];

__device__ __forceinline__ void mma_f16(float c[4], const uint32_t a[4], const uint32_t b[2]) {
    asm volatile(
        "mma.sync.aligned.m16n8k16.row.col.f32.f16.f16.f32 "
        "{%0,%1,%2,%3}, {%4,%5,%6,%7}, {%8,%9}, {%0,%1,%2,%3};\n"
        : "+f"(c[0]), "+f"(c[1]), "+f"(c[2]), "+f"(c[3])
        : "r"(a[0]), "r"(a[1]), "r"(a[2]), "r"(a[3]), "r"(b[0]), "r"(b[1]));
}

__device__ __forceinline__ float silu_f(float g) {
    return g / (1.f + expf(-g));
}

__device__ __forceinline__ uint2 pack4(float4 v) {
    __half2 lo = __floats2half2_rn(v.x, v.y);
    __half2 hi = __floats2half2_rn(v.z, v.w);
    uint2 r;
    r.x = *(uint32_t*)&lo;
    r.y = *(uint32_t*)&hi;
    return r;
}

__device__ __forceinline__ uint32_t smem_u32(const void* p) {
    uint32_t a;
    asm("{ .reg .u64 t; cvta.to.shared.u64 t, %1; cvt.u32.u64 %0, t; }" : "=r"(a) : "l"(p));
    return a;
}
#define CP_ASYNC16(dst, src) \
    asm volatile("cp.async.cg.shared.global [%0], [%1], 16;" :: "r"(dst), "l"(src) : "memory")
#define CP_COMMIT() asm volatile("cp.async.commit_group;" ::: "memory")
#define CP_WAIT1()  asm volatile("cp.async.wait_group 1;" ::: "memory")

// ---------------- fp32 -> fp16 conversion (once per call) ----------------
// DST: 0 = g_xh, 1 = g_gwh, 2 = g_uwh, 3 = g_dwh  (no host symbol lookup needed)
template <int DST>
__global__ void cvt_kernel(const float4* __restrict__ src, int n4) {
    int i = blockIdx.x * blockDim.x + threadIdx.x;
    if (i >= n4) return;
    uint2* dst = (DST == 0) ? (uint2*)g_xh
               : (DST == 1) ? (uint2*)g_gwh
               : (DST == 2) ? (uint2*)g_uwh
                            : (uint2*)g_dwh;
    dst[i] = pack4(src[i]);
}

// ---------------- routing ----------------
__global__ void router_kernel(const float* __restrict__ x, const float* __restrict__ rw) {
    __shared__ float s_rw[E_NUM * H_DIM];  // 32 KB
    int tid = threadIdx.x;
    for (int i = tid; i < E_NUM * H_DIM; i += blockDim.x) s_rw[i] = rw[i];
    __syncthreads();
    int wid = tid >> 5, lane = tid & 31;
    int t = blockIdx.x * 8 + wid;
    const float* xr = x + (size_t)t * H_DIM;
    float acc[E_NUM];
#pragma unroll
    for (int e = 0; e < E_NUM; e++) acc[e] = 0.f;
    for (int h = lane; h < H_DIM; h += 32) {
        float xv = xr[h];
#pragma unroll
        for (int e = 0; e < E_NUM; e++) acc[e] += xv * s_rw[e * H_DIM + h];
    }
#pragma unroll
    for (int e = 0; e < E_NUM; e++) {
#pragma unroll
        for (int o = 16; o > 0; o >>= 1) acc[e] += __shfl_xor_sync(0xffffffff, acc[e], o);
    }
    if (lane == 0) {
        float m = acc[0];
#pragma unroll
        for (int e = 1; e < E_NUM; e++) m = fmaxf(m, acc[e]);
        float p[E_NUM], s = 0.f;
#pragma unroll
        for (int e = 0; e < E_NUM; e++) { p[e] = expf(acc[e] - m); s += p[e]; }
        float inv = 1.f / s;
        int i0 = 0; float v0 = p[0];
#pragma unroll
        for (int e = 1; e < E_NUM; e++) if (p[e] > v0) { v0 = p[e]; i0 = e; }
        int i1 = -1; float v1 = -1.f;
#pragma unroll
        for (int e = 0; e < E_NUM; e++) if (e != i0 && p[e] > v1) { v1 = p[e]; i1 = e; }
        g_assign_eid[t * 2 + 0] = i0;
        g_assign_eid[t * 2 + 1] = i1;
        g_assign_wt[t * 2 + 0] = v0 * inv;
        g_assign_wt[t * 2 + 1] = v1 * inv;
    }
}

// single block: count + scan + scatter
__global__ void bucket_kernel() {
    __shared__ int s_cnt[E_NUM], s_fill[E_NUM];
    int tid = threadIdx.x;
    if (tid < E_NUM) s_cnt[tid] = 0;
    __syncthreads();
    for (int i = tid; i < SLOTS; i += blockDim.x)
        atomicAdd(&s_cnt[g_assign_eid[i]], 1);
    __syncthreads();
    if (tid == 0) {
        int off = 0;
        for (int e = 0; e < E_NUM; e++) {
            g_offsets[e] = off;
            g_counts[e] = s_cnt[e];
            s_fill[e] = off;
            off += s_cnt[e];
        }
    }
    __syncthreads();
    for (int i = tid; i < SLOTS; i += blockDim.x) {
        int e = g_assign_eid[i];
        int slot = atomicAdd(&s_fill[e], 1);
        g_slot_token[slot] = i >> 1;
        g_slot_wt[slot] = g_assign_wt[i];
    }
}

__global__ void zero_out_kernel(float* __restrict__ out) {
    int i = blockIdx.x * blockDim.x + threadIdx.x;
    if (i < T_NUM * H_DIM / 4) ((float4*)out)[i] = make_float4(0.f, 0.f, 0.f, 0.f);
}

// -- grouped TN GEMM, fp16 mma, cp.async 3-stage ring (all-fp16 data), 2 CTAs/SM --
// C[m,n] = sum_k A[m,k] * B[e][n,k]; fp32 accumulate in tensor core.
// MODE 0: gate  (A = g_xh gathered via slot_token, B = g_gwh) -> g_gbuf (fp32)
// MODE 1: up    (A = g_xh gathered, B = g_uwh)  epilogue h = silu(g_gbuf)*u -> g_hbuf
// MODE 2: down  (A = g_hbuf slot rows, B = g_dwh) epilogue out[token] += w * y (atomic)
template <int KDIM, int MODE>
__global__ __launch_bounds__(256, 2)
void gemm_tn_kernel(float* __restrict__ OUT, int NDIM) {
    extern __shared__ __half smh[];

    const __half* Ah    = (MODE == 2) ? g_hbuf : g_xh;
    const __half* Bfull = (MODE == 0) ? g_gwh : (MODE == 1) ? g_uwh : g_dwh;

    const int e   = blockIdx.z;
    const int cnt = g_counts[e];
    const int off = g_offsets[e];
    const int m0  = blockIdx.x * 128;
    if (m0 >= cnt) return;
    const int n0  = blockIdx.y * 128;

    const int tid  = threadIdx.x;
    const int wid  = tid >> 5;
    const int lane = tid & 31;
    const int wm   = wid >> 2;   // 0..1 (64 rows each)
    const int wn   = wid & 3;    // 0..3 (32 cols each)
    const int g    = lane >> 2;  // 0..7
    const int tig  = lane & 3;   // 0..3

    const __half* Bw = Bfull + (size_t)e * NDIM * KDIM + (size_t)n0 * KDIM;

    // staging: per thread 2 chunks (16B = 8 halfs) per operand per tile.
    // chunk = j*256 + tid -> row = chunk>>2, kc = (chunk&3)*8
    const __half* abase[2];
    const __half* bbase[2];
    uint32_t dstA[2], dstB[2];
    const uint32_t sm0 = smem_u32(smh);
#pragma unroll
    for (int j = 0; j < 2; j++) {
        int chunk = j * 256 + tid;
        int r  = chunk >> 2;          // 0..127
        int kc = (chunk & 3) * 8;     // 0,8,16,24 halfs
        int mi = m0 + r;
        int grow;
        if (MODE != 2) {
            grow = g_slot_token[off + ((mi < cnt) ? mi : (cnt - 1))];
        } else {
            grow = off + ((mi < cnt) ? mi : (cnt - 1));
        }
        abase[j] = Ah + (size_t)grow * KDIM + kc;
        bbase[j] = Bw + (size_t)r * KDIM + kc;
        dstA[j] = (uint32_t)((r * PH + kc) * 2);
        dstB[j] = dstA[j] + (uint32_t)(AS_H * 2);
    }

    auto issue_tile = [&](int kt) {
        const uint32_t st = sm0 + (uint32_t)((kt % N_STAGE) * STAGE_H * 2);
        const int ko = kt * 32;   // halfs
#pragma unroll
        for (int j = 0; j < 2; j++) CP_ASYNC16(st + dstA[j], abase[j] + ko);
#pragma unroll
        for (int j = 0; j < 2; j++) CP_ASYNC16(st + dstB[j], bbase[j] + ko);
    };

    float c[4][4][4];
#pragma unroll
    for (int mt = 0; mt < 4; mt++)
#pragma unroll
        for (int nt = 0; nt < 4; nt++)
#pragma unroll
            for (int j = 0; j < 4; j++) c[mt][nt][j] = 0.f;

    constexpr int KT = KDIM / 32;
    issue_tile(0); CP_COMMIT();
    issue_tile(1); CP_COMMIT();

    for (int kt = 0; kt < KT; kt++) {
        CP_WAIT1();          // own copies of tile kt landed
        __syncthreads();     // all copies of tile kt visible; every warp finished
                             // mma(kt-1), so ring stage (kt+2)%3 is free
        if (kt + 2 < KT) issue_tile(kt + 2);
        CP_COMMIT();         // (possibly empty) group keeps pending count in step

        const __half* sA = smh + (kt % N_STAGE) * STAGE_H;
        const __half* sB = sA + AS_H;
#pragma unroll
        for (int ks = 0; ks < 2; ks++) {
            const int kk = ks * 16;
            uint32_t af[4][4], bf[4][2];
#pragma unroll
            for (int mt = 0; mt < 4; mt++) {
                int m = wm * 64 + mt * 16;
                const __half* a0 = &sA[(m + g) * PH + kk + 2 * tig];
                const __half* a1 = &sA[(m + g + 8) * PH + kk + 2 * tig];
                af[mt][0] = *(const uint32_t*)(a0);
                af[mt][1] = *(const uint32_t*)(a1);
                af[mt][2] = *(const uint32_t*)(a0 + 8);
                af[mt][3] = *(const uint32_t*)(a1 + 8);
            }
#pragma unroll
            for (int nt = 0; nt < 4; nt++) {
                int n = wn * 32 + nt * 8;
                const __half* b0 = &sB[(n + g) * PH + kk + 2 * tig];
                bf[nt][0] = *(const uint32_t*)(b0);
                bf[nt][1] = *(const uint32_t*)(b0 + 8);
            }
#pragma unroll
            for (int mt = 0; mt < 4; mt++)
#pragma unroll
                for (int nt = 0; nt < 4; nt++)
                    mma_f16(c[mt][nt], af[mt], bf[nt]);
        }
    }

    // ---------------- epilogue ----------------
    const int cntloc = cnt - m0;
#pragma unroll
    for (int mt = 0; mt < 4; mt++) {
        const int r_lo = wm * 64 + mt * 16 + g;
        const int r_hi = r_lo + 8;
        const bool v_lo = r_lo < cntloc;
        const bool v_hi = r_hi < cntloc;

        if (MODE == 2) {
            int slot_lo = off + m0 + (v_lo ? r_lo : 0);
            int slot_hi = off + m0 + (v_hi ? r_hi : 0);
            int   tok_lo = g_slot_token[slot_lo];
            int   tok_hi = g_slot_token[slot_hi];
            float w_lo   = g_slot_wt[slot_lo];
            float w_hi   = g_slot_wt[slot_hi];
#pragma unroll
            for (int nt = 0; nt < 4; nt++) {
                int col = n0 + wn * 32 + nt * 8 + 2 * tig;
                if (v_lo) {
                    float* p = OUT + (size_t)tok_lo * H_DIM + col;
                    atomicAdd(p + 0, w_lo * c[mt][nt][0]);
                    atomicAdd(p + 1, w_lo * c[mt][nt][1]);
                }
                if (v_hi) {
                    float* p = OUT + (size_t)tok_hi * H_DIM + col;
                    atomicAdd(p + 0, w_hi * c[mt][nt][2]);
                    atomicAdd(p + 1, w_hi * c[mt][nt][3]);
                }
            }
        } else {
#pragma unroll
            for (int nt = 0; nt < 4; nt++) {
                int col = n0 + wn * 32 + nt * 8 + 2 * tig;
                size_t idx_lo = (size_t)(off + m0 + r_lo) * I_DIM + col;
                size_t idx_hi = (size_t)(off + m0 + r_hi) * I_DIM + col;
                if (MODE == 0) {
                    if (v_lo) {
                        g_gbuf[idx_lo + 0] = c[mt][nt][0];
                        g_gbuf[idx_lo + 1] = c[mt][nt][1];
                    }
                    if (v_hi) {
                        g_gbuf[idx_hi + 0] = c[mt][nt][2];
                        g_gbuf[idx_hi + 1] = c[mt][nt][3];
                    }
                } else {  // MODE 1: h = silu(g) * u -> fp16
                    if (v_lo) {
                        float2 gv = *(const float2*)(g_gbuf + idx_lo);
                        __half2 h = __floats2half2_rn(silu_f(gv.x) * c[mt][nt][0],
                                                      silu_f(gv.y) * c[mt][nt][1]);
                        *(__half2*)(g_hbuf + idx_lo) = h;
                    }
                    if (v_hi) {
                        float2 gv = *(const float2*)(g_gbuf + idx_hi);
                        __half2 h = __floats2half2_rn(silu_f(gv.x) * c[mt][nt][2],
                                                      silu_f(gv.y) * c[mt][nt][3]);
                        *(__half2*)(g_hbuf + idx_hi) = h;
                    }
                }
            }
        }
    }
}

// ---------------- launch ----------------
extern "C" void kernel_launch(void* const* d_in, const int* in_sizes, int n_in,
                              void* d_out, int out_size) {
    const float* x  = (const float*)d_in[0];   // [2048,1024]
    const float* rw = (const float*)d_in[1];   // [8,1024]
    const float* gw = (const float*)d_in[2];   // [8,2816,1024]
    const float* uw = (const float*)d_in[3];   // [8,2816,1024]
    const float* dw = (const float*)d_in[4];   // [8,1024,2816]
    float* out = (float*)d_out;                // [2048,1024]

    cudaFuncSetAttribute(gemm_tn_kernel<H_DIM, 0>,
                         cudaFuncAttributeMaxDynamicSharedMemorySize, SMEM_BYTES);
    cudaFuncSetAttribute(gemm_tn_kernel<H_DIM, 1>,
                         cudaFuncAttributeMaxDynamicSharedMemorySize, SMEM_BYTES);
    cudaFuncSetAttribute(gemm_tn_kernel<I_DIM, 2>,
                         cudaFuncAttributeMaxDynamicSharedMemorySize, SMEM_BYTES);

    const int W4 = E_NUM * I_DIM * H_DIM / 4;   // 5,767,168
    const int X4 = T_NUM * H_DIM / 4;           // 524,288
    cvt_kernel<0><<<(X4 + 255) / 256, 256>>>((const float4*)x,  X4);
    cvt_kernel<1><<<(W4 + 255) / 256, 256>>>((const float4*)gw, W4);
    cvt_kernel<2><<<(W4 + 255) / 256, 256>>>((const float4*)uw, W4);
    cvt_kernel<3><<<(W4 + 255) / 256, 256>>>((const float4*)dw, W4);

    router_kernel<<<T_NUM / 8, 256>>>(x, rw);
    bucket_kernel<<<1, 512>>>();
    zero_out_kernel<<<(T_NUM * H_DIM / 4 + 255) / 256, 256>>>(out);

    // gate: [slots] x [I] = x @ gate_w^T
    gemm_tn_kernel<H_DIM, 0><<<dim3(SLOTS / 128, I_DIM / 128, E_NUM), 256, SMEM_BYTES>>>(
        nullptr, I_DIM);
    // up + fused silu: h = silu(g) * (x @ up_w^T)
    gemm_tn_kernel<H_DIM, 1><<<dim3(SLOTS / 128, I_DIM / 128, E_NUM), 256, SMEM_BYTES>>>(
        nullptr, I_DIM);
    // down + fused weighted combine
    gemm_tn_kernel<I_DIM, 2><<<dim3(SLOTS / 128, H_DIM / 128, E_NUM), 256, SMEM_BYTES>>>(
        out, H_DIM);
}

// round 17
// speedup vs baseline: 1.0941x; 1.0941x over previous
#include <cuda_runtime.h>
#include <cuda_fp16.h>
#include <cstdint>
#include <cmath>

#define H_DIM 1024
#define I_DIM 2816
#define E_NUM 8
#define T_NUM 2048
#define SLOTS (T_NUM * 2)   // 4096 (every token has exactly 2 expert assignments)

// SMEM (half): 3-stage ring x (A 128x40 + B 128x40) halfs.
// PH=40 halfs = 80 B. cp.async 16B dst aligned; ldmatrix row addresses mod 128B
// = {0,80,32,112,64,16,96,48} -> conflict-free.
static constexpr int PH        = 40;
static constexpr int AS_H      = 128 * PH;            // 5120 halfs per operand
static constexpr int STAGE_H   = 2 * AS_H;            // 10240 halfs per stage
static constexpr int N_STAGE   = 3;
static constexpr int SMEM_BYTES = N_STAGE * STAGE_H * 2;  // 61440 B (x2 CTAs = 120KB/SM)

// ---------------- scratch (static __device__, allocation-free) ----------------
__device__ __half g_xh[T_NUM * H_DIM];          // x in fp16
__device__ __half g_gwh[E_NUM * I_DIM * H_DIM]; // gate_w fp16
__device__ __half g_uwh[E_NUM * I_DIM * H_DIM]; // up_w fp16
__device__ __half g_dwh[E_NUM * H_DIM * I_DIM]; // down_w fp16
__device__ float  g_gbuf[SLOTS * I_DIM];        // gate GEMM out (fp32, silu input)
__device__ __half g_hbuf[SLOTS * I_DIM];        // h = silu(gate)*up, fp16
__device__ int    g_counts[E_NUM];
__device__ int    g_offsets[E_NUM];
__device__ int    g_slot_token[SLOTS];
__device__ float  g_slot_wt[SLOTS];
__device__ int    g_assign_eid[SLOTS];
__device__ float  g_assign_wt[SLOTS];

__device__ __forceinline__ void mma_f16(float c[4], const uint32_t a[4], const uint32_t b[2]) {
    asm volatile(
        "mma.sync.aligned.m16n8k16.row.col.f32.f16.f16.f32 "
        "{%0,%1,%2,%3}, {%4,%5,%6,%7}, {%8,%9}, {%0,%1,%2,%3};\n"
        : "+f"(c[0]), "+f"(c[1]), "+f"(c[2]), "+f"(c[3])
        : "r"(a[0]), "r"(a[1]), "r"(a[2]), "r"(a[3]), "r"(b[0]), "r"(b[1]));
}

__device__ __forceinline__ void ldsm_x4(uint32_t& r0, uint32_t& r1,
                                        uint32_t& r2, uint32_t& r3, uint32_t addr) {
    asm volatile("ldmatrix.sync.aligned.m8n8.x4.shared.b16 {%0,%1,%2,%3}, [%4];"
                 : "=r"(r0), "=r"(r1), "=r"(r2), "=r"(r3) : "r"(addr));
}

__device__ __forceinline__ float silu_f(float g) {
    return g / (1.f + expf(-g));
}

__device__ __forceinline__ uint2 pack4(float4 v) {
    __half2 lo = __floats2half2_rn(v.x, v.y);
    __half2 hi = __floats2half2_rn(v.z, v.w);
    uint2 r;
    r.x = *(uint32_t*)&lo;
    r.y = *(uint32_t*)&hi;
    return r;
}

__device__ __forceinline__ uint32_t smem_u32(const void* p) {
    uint32_t a;
    asm("{ .reg .u64 t; cvta.to.shared.u64 t, %1; cvt.u32.u64 %0, t; }" : "=r"(a) : "l"(p));
    return a;
}
#define CP_ASYNC16(dst, src) \
    asm volatile("cp.async.cg.shared.global [%0], [%1], 16;" :: "r"(dst), "l"(src) : "memory")
#define CP_COMMIT() asm volatile("cp.async.commit_group;" ::: "memory")
#define CP_WAIT1()  asm volatile("cp.async.wait_group 1;" ::: "memory")

// ---------------- fp32 -> fp16 conversion (once per call) ----------------
// DST: 0 = g_xh, 1 = g_gwh, 2 = g_uwh, 3 = g_dwh
template <int DST>
__global__ void cvt_kernel(const float4* __restrict__ src, int n4) {
    int i = blockIdx.x * blockDim.x + threadIdx.x;
    if (i >= n4) return;
    uint2* dst = (DST == 0) ? (uint2*)g_xh
               : (DST == 1) ? (uint2*)g_gwh
               : (DST == 2) ? (uint2*)g_uwh
                            : (uint2*)g_dwh;
    dst[i] = pack4(src[i]);
}

// ---------------- routing ----------------
__global__ void router_kernel(const float* __restrict__ x, const float* __restrict__ rw) {
    __shared__ float s_rw[E_NUM * H_DIM];  // 32 KB
    int tid = threadIdx.x;
    for (int i = tid; i < E_NUM * H_DIM; i += blockDim.x) s_rw[i] = rw[i];
    __syncthreads();
    int wid = tid >> 5, lane = tid & 31;
    int t = blockIdx.x * 8 + wid;
    const float* xr = x + (size_t)t * H_DIM;
    float acc[E_NUM];
#pragma unroll
    for (int e = 0; e < E_NUM; e++) acc[e] = 0.f;
    for (int h = lane; h < H_DIM; h += 32) {
        float xv = xr[h];
#pragma unroll
        for (int e = 0; e < E_NUM; e++) acc[e] += xv * s_rw[e * H_DIM + h];
    }
#pragma unroll
    for (int e = 0; e < E_NUM; e++) {
#pragma unroll
        for (int o = 16; o > 0; o >>= 1) acc[e] += __shfl_xor_sync(0xffffffff, acc[e], o);
    }
    if (lane == 0) {
        float m = acc[0];
#pragma unroll
        for (int e = 1; e < E_NUM; e++) m = fmaxf(m, acc[e]);
        float p[E_NUM], s = 0.f;
#pragma unroll
        for (int e = 0; e < E_NUM; e++) { p[e] = expf(acc[e] - m); s += p[e]; }
        float inv = 1.f / s;
        int i0 = 0; float v0 = p[0];
#pragma unroll
        for (int e = 1; e < E_NUM; e++) if (p[e] > v0) { v0 = p[e]; i0 = e; }
        int i1 = -1; float v1 = -1.f;
#pragma unroll
        for (int e = 0; e < E_NUM; e++) if (e != i0 && p[e] > v1) { v1 = p[e]; i1 = e; }
        g_assign_eid[t * 2 + 0] = i0;
        g_assign_eid[t * 2 + 1] = i1;
        g_assign_wt[t * 2 + 0] = v0 * inv;
        g_assign_wt[t * 2 + 1] = v1 * inv;
    }
}

// single block: count + scan + scatter
__global__ void bucket_kernel() {
    __shared__ int s_cnt[E_NUM], s_fill[E_NUM];
    int tid = threadIdx.x;
    if (tid < E_NUM) s_cnt[tid] = 0;
    __syncthreads();
    for (int i = tid; i < SLOTS; i += blockDim.x)
        atomicAdd(&s_cnt[g_assign_eid[i]], 1);
    __syncthreads();
    if (tid == 0) {
        int off = 0;
        for (int e = 0; e < E_NUM; e++) {
            g_offsets[e] = off;
            g_counts[e] = s_cnt[e];
            s_fill[e] = off;
            off += s_cnt[e];
        }
    }
    __syncthreads();
    for (int i = tid; i < SLOTS; i += blockDim.x) {
        int e = g_assign_eid[i];
        int slot = atomicAdd(&s_fill[e], 1);
        g_slot_token[slot] = i >> 1;
        g_slot_wt[slot] = g_assign_wt[i];
    }
}

__global__ void zero_out_kernel(float* __restrict__ out) {
    int i = blockIdx.x * blockDim.x + threadIdx.x;
    if (i < T_NUM * H_DIM / 4) ((float4*)out)[i] = make_float4(0.f, 0.f, 0.f, 0.f);
}

// -- grouped TN GEMM, fp16 mma + ldmatrix frags, cp.async 3-stage ring, 2 CTAs/SM --
// C[m,n] = sum_k A[m,k] * B[e][n,k]; fp32 accumulate in tensor core.
// MODE 0: gate  (A = g_xh gathered via slot_token, B = g_gwh) -> g_gbuf (fp32)
// MODE 1: up    (A = g_xh gathered, B = g_uwh)  epilogue h = silu(g_gbuf)*u -> g_hbuf
// MODE 2: down  (A = g_hbuf slot rows, B = g_dwh) epilogue out[token] += w * y (atomic)
template <int KDIM, int MODE>
__global__ __launch_bounds__(256, 2)
void gemm_tn_kernel(float* __restrict__ OUT, int NDIM) {
    extern __shared__ __half smh[];

    const __half* Ah    = (MODE == 2) ? g_hbuf : g_xh;
    const __half* Bfull = (MODE == 0) ? g_gwh : (MODE == 1) ? g_uwh : g_dwh;

    const int e   = blockIdx.z;
    const int cnt = g_counts[e];
    const int off = g_offsets[e];
    const int m0  = blockIdx.x * 128;
    if (m0 >= cnt) return;
    const int n0  = blockIdx.y * 128;

    const int tid  = threadIdx.x;
    const int wid  = tid >> 5;
    const int lane = tid & 31;
    const int wm   = wid >> 2;   // 0..1 (64 rows each)
    const int wn   = wid & 3;    // 0..3 (32 cols each)
    const int g    = lane >> 2;  // 0..7
    const int tig  = lane & 3;   // 0..3

    const __half* Bw = Bfull + (size_t)e * NDIM * KDIM + (size_t)n0 * KDIM;

    // staging: per thread 2 chunks (16B = 8 halfs) per operand per tile.
    const __half* abase[2];
    const __half* bbase[2];
    uint32_t dstA[2], dstB[2];
    const uint32_t sm0 = smem_u32(smh);
#pragma unroll
    for (int j = 0; j < 2; j++) {
        int chunk = j * 256 + tid;
        int r  = chunk >> 2;          // 0..127
        int kc = (chunk & 3) * 8;     // 0,8,16,24 halfs
        int mi = m0 + r;
        int grow;
        if (MODE != 2) {
            grow = g_slot_token[off + ((mi < cnt) ? mi : (cnt - 1))];
        } else {
            grow = off + ((mi < cnt) ? mi : (cnt - 1));
        }
        abase[j] = Ah + (size_t)grow * KDIM + kc;
        bbase[j] = Bw + (size_t)r * KDIM + kc;
        dstA[j] = (uint32_t)((r * PH + kc) * 2);
        dstB[j] = dstA[j] + (uint32_t)(AS_H * 2);
    }

    auto issue_tile = [&](int kt) {
        const uint32_t st = sm0 + (uint32_t)((kt % N_STAGE) * STAGE_H * 2);
        const int ko = kt * 32;   // halfs
#pragma unroll
        for (int j = 0; j < 2; j++) CP_ASYNC16(st + dstA[j], abase[j] + ko);
#pragma unroll
        for (int j = 0; j < 2; j++) CP_ASYNC16(st + dstB[j], bbase[j] + ko);
    };

    // ldmatrix per-lane base offsets (bytes within a stage), k-invariant parts.
    // A (x4, matrices: (m,kk),(m+8,kk),(m,kk+8),(m+8,kk+8)):
    //   row = m + (lane&7) + ((lane>>3)&1)*8, col = (lane>>4)*8
    // B (x4, matrices: (n,kk),(n,kk+8),(n+8,kk),(n+8,kk+8)):
    //   row = n + (lane&7) + (lane>>4)*8,     col = ((lane>>3)&1)*8
    const int rA = (lane & 7) + ((lane >> 3) & 1) * 8;
    const int cA = (lane >> 4) * 8;
    const int rB = (lane & 7) + (lane >> 4) * 8;
    const int cB = ((lane >> 3) & 1) * 8;
    uint32_t aBase[4], bBase[2];
#pragma unroll
    for (int mt = 0; mt < 4; mt++)
        aBase[mt] = (uint32_t)(((wm * 64 + mt * 16 + rA) * PH + cA) * 2);
#pragma unroll
    for (int j = 0; j < 2; j++)
        bBase[j] = (uint32_t)((AS_H + (wn * 32 + j * 16 + rB) * PH + cB) * 2);

    float c[4][4][4];
#pragma unroll
    for (int mt = 0; mt < 4; mt++)
#pragma unroll
        for (int nt = 0; nt < 4; nt++)
#pragma unroll
            for (int j = 0; j < 4; j++) c[mt][nt][j] = 0.f;

    constexpr int KT = KDIM / 32;
    issue_tile(0); CP_COMMIT();
    issue_tile(1); CP_COMMIT();

    for (int kt = 0; kt < KT; kt++) {
        CP_WAIT1();          // own copies of tile kt landed
        __syncthreads();     // all copies visible; stage (kt+2)%3 drained
        if (kt + 2 < KT) issue_tile(kt + 2);
        CP_COMMIT();         // keep pending-group count in step

        const uint32_t st = sm0 + (uint32_t)((kt % N_STAGE) * STAGE_H * 2);
#pragma unroll
        for (int ks = 0; ks < 2; ks++) {
            const uint32_t kb = (uint32_t)(ks * 32);  // 16 halfs = 32 B
            uint32_t af[4][4], bf[4][2];
#pragma unroll
            for (int mt = 0; mt < 4; mt++)
                ldsm_x4(af[mt][0], af[mt][1], af[mt][2], af[mt][3], st + aBase[mt] + kb);
            ldsm_x4(bf[0][0], bf[0][1], bf[1][0], bf[1][1], st + bBase[0] + kb);
            ldsm_x4(bf[2][0], bf[2][1], bf[3][0], bf[3][1], st + bBase[1] + kb);
#pragma unroll
            for (int mt = 0; mt < 4; mt++)
#pragma unroll
                for (int nt = 0; nt < 4; nt++)
                    mma_f16(c[mt][nt], af[mt], bf[nt]);
        }
    }

    // ---------------- epilogue ----------------
    const int cntloc = cnt - m0;
#pragma unroll
    for (int mt = 0; mt < 4; mt++) {
        const int r_lo = wm * 64 + mt * 16 + g;
        const int r_hi = r_lo + 8;
        const bool v_lo = r_lo < cntloc;
        const bool v_hi = r_hi < cntloc;

        if (MODE == 2) {
            int slot_lo = off + m0 + (v_lo ? r_lo : 0);
            int slot_hi = off + m0 + (v_hi ? r_hi : 0);
            int   tok_lo = g_slot_token[slot_lo];
            int   tok_hi = g_slot_token[slot_hi];
            float w_lo   = g_slot_wt[slot_lo];
            float w_hi   = g_slot_wt[slot_hi];
#pragma unroll
            for (int nt = 0; nt < 4; nt++) {
                int col = n0 + wn * 32 + nt * 8 + 2 * tig;
                if (v_lo) {
                    float* p = OUT + (size_t)tok_lo * H_DIM + col;
                    atomicAdd(p + 0, w_lo * c[mt][nt][0]);
                    atomicAdd(p + 1, w_lo * c[mt][nt][1]);
                }
                if (v_hi) {
                    float* p = OUT + (size_t)tok_hi * H_DIM + col;
                    atomicAdd(p + 0, w_hi * c[mt][nt][2]);
                    atomicAdd(p + 1, w_hi * c[mt][nt][3]);
                }
            }
        } else {
#pragma unroll
            for (int nt = 0; nt < 4; nt++) {
                int col = n0 + wn * 32 + nt * 8 + 2 * tig;
                size_t idx_lo = (size_t)(off + m0 + r_lo) * I_DIM + col;
                size_t idx_hi = (size_t)(off + m0 + r_hi) * I_DIM + col;
                if (MODE == 0) {
                    if (v_lo) {
                        g_gbuf[idx_lo + 0] = c[mt][nt][0];
                        g_gbuf[idx_lo + 1] = c[mt][nt][1];
                    }
                    if (v_hi) {
                        g_gbuf[idx_hi + 0] = c[mt][nt][2];
                        g_gbuf[idx_hi + 1] = c[mt][nt][3];
                    }
                } else {  // MODE 1: h = silu(g) * u -> fp16
                    if (v_lo) {
                        float2 gv = *(const float2*)(g_gbuf + idx_lo);
                        __half2 h = __floats2half2_rn(silu_f(gv.x) * c[mt][nt][0],
                                                      silu_f(gv.y) * c[mt][nt][1]);
                        *(__half2*)(g_hbuf + idx_lo) = h;
                    }
                    if (v_hi) {
                        float2 gv = *(const float2*)(g_gbuf + idx_hi);
                        __half2 h = __floats2half2_rn(silu_f(gv.x) * c[mt][nt][2],
                                                      silu_f(gv.y) * c[mt][nt][3]);
                        *(__half2*)(g_hbuf + idx_hi) = h;
                    }
                }
            }
        }
    }
}

// ---------------- launch ----------------
extern "C" void kernel_launch(void* const* d_in, const int* in_sizes, int n_in,
                              void* d_out, int out_size) {
    const float* x  = (const float*)d_in[0];   // [2048,1024]
    const float* rw = (const float*)d_in[1];   // [8,1024]
    const float* gw = (const float*)d_in[2];   // [8,2816,1024]
    const float* uw = (const float*)d_in[3];   // [8,2816,1024]
    const float* dw = (const float*)d_in[4];   // [8,1024,2816]
    float* out = (float*)d_out;                // [2048,1024]

    cudaFuncSetAttribute(gemm_tn_kernel<H_DIM, 0>,
                         cudaFuncAttributeMaxDynamicSharedMemorySize, SMEM_BYTES);
    cudaFuncSetAttribute(gemm_tn_kernel<H_DIM, 1>,
                         cudaFuncAttributeMaxDynamicSharedMemorySize, SMEM_BYTES);
    cudaFuncSetAttribute(gemm_tn_kernel<I_DIM, 2>,
                         cudaFuncAttributeMaxDynamicSharedMemorySize, SMEM_BYTES);

    const int W4 = E_NUM * I_DIM * H_DIM / 4;   // 5,767,168
    const int X4 = T_NUM * H_DIM / 4;           // 524,288
    cvt_kernel<0><<<(X4 + 255) / 256, 256>>>((const float4*)x,  X4);
    cvt_kernel<1><<<(W4 + 255) / 256, 256>>>((const float4*)gw, W4);
    cvt_kernel<2><<<(W4 + 255) / 256, 256>>>((const float4*)uw, W4);
    cvt_kernel<3><<<(W4 + 255) / 256, 256>>>((const float4*)dw, W4);

    router_kernel<<<T_NUM / 8, 256>>>(x, rw);
    bucket_kernel<<<1, 512>>>();
    zero_out_kernel<<<(T_NUM * H_DIM / 4 + 255) / 256, 256>>>(out);

    // gate: [slots] x [I] = x @ gate_w^T
    gemm_tn_kernel<H_DIM, 0><<<dim3(SLOTS / 128, I_DIM / 128, E_NUM), 256, SMEM_BYTES>>>(
        nullptr, I_DIM);
    // up + fused silu: h = silu(g) * (x @ up_w^T)
    gemm_tn_kernel<H_DIM, 1><<<dim3(SLOTS / 128, I_DIM / 128, E_NUM), 256, SMEM_BYTES>>>(
        nullptr, I_DIM);
    // down + fused weighted combine
    gemm_tn_kernel<I_DIM, 2><<<dim3(SLOTS / 128, H_DIM / 128, E_NUM), 256, SMEM_BYTES>>>(
        out, H_DIM);
}